// round 13
// baseline (speedup 1.0000x reference)
#include <cuda_runtime.h>

// ---------------------------------------------------------------------------
#define P_ELEMS (96*96*96)          // 884736 points per sample
#define NSAMP   4
#define NB      32
#define NBINS2  (NB*NB)
#define MM_CTAS 74                  // minmax CTAs per sample
#define H_CTAS  37                  // hist CTAs per sample (37*4=148, 1/SM)
#define HTHR    512                 // hist threads per CTA (128-reg budget)
#define NCOPY   32                  // lane copies per hist CTA (128 KB)
#define HSTEP   (H_CTAS*HTHR)       // 18944 float4s per grid-stride step

// C = 2048/961 = 2.1311134235 ; exp2 form: C*log2(e)
#define EXP2_C   3.0745468f
#define EXP2_2C  6.1490936f
#define EPS      1e-10f

// ---------------------------------------------------------------------------
// Device scratch (no allocations allowed)
__device__ float    g_pmnT[NSAMP*MM_CTAS];
__device__ float    g_pmxT[NSAMP*MM_CTAS];
__device__ float    g_pmnS[NSAMP*MM_CTAS];
__device__ float    g_pmxS[NSAMP*MM_CTAS];
__device__ float    g_hist[NSAMP*NBINS2];
__device__ unsigned g_tick = 0;     // hist completion ticket

// ---------------------------------------------------------------------------
// Pass 1: per-CTA min/max partials. Batched independent LDG.128 for MLP.
__global__ void __launch_bounds__(1024) k_pre(const float* __restrict__ tar,
                                              const float* __restrict__ src) {
    int b = blockIdx.y;
    if (b == 0) {
        int idx = blockIdx.x * 1024 + threadIdx.x;
        if (idx < NSAMP * NBINS2) g_hist[idx] = 0.0f;
    }

    const float4* t4 = (const float4*)(tar + (size_t)b * P_ELEMS);
    const float4* s4 = (const float4*)(src + (size_t)b * P_ELEMS);
    const int n4 = P_ELEMS / 4;                 // 221184
    const int stride = MM_CTAS * 1024;          // 75776

    const int i = blockIdx.x * 1024 + threadIdx.x;
    float4 a0 = t4[i],          c0 = s4[i];
    float4 a1 = t4[i + stride], c1 = s4[i + stride];

    float mnT = fminf(fminf(fminf(a0.x, a0.y), fminf(a0.z, a0.w)),
                      fminf(fminf(a1.x, a1.y), fminf(a1.z, a1.w)));
    float mxT = fmaxf(fmaxf(fmaxf(a0.x, a0.y), fmaxf(a0.z, a0.w)),
                      fmaxf(fmaxf(a1.x, a1.y), fmaxf(a1.z, a1.w)));
    float mnS = fminf(fminf(fminf(c0.x, c0.y), fminf(c0.z, c0.w)),
                      fminf(fminf(c1.x, c1.y), fminf(c1.z, c1.w)));
    float mxS = fmaxf(fmaxf(fmaxf(c0.x, c0.y), fmaxf(c0.z, c0.w)),
                      fmaxf(fmaxf(c1.x, c1.y), fmaxf(c1.z, c1.w)));

    const int i2 = i + 2 * stride;
    if (i2 < n4) {
        float4 a2 = t4[i2], c2 = s4[i2];
        mnT = fminf(mnT, fminf(fminf(a2.x, a2.y), fminf(a2.z, a2.w)));
        mxT = fmaxf(mxT, fmaxf(fmaxf(a2.x, a2.y), fmaxf(a2.z, a2.w)));
        mnS = fminf(mnS, fminf(fminf(c2.x, c2.y), fminf(c2.z, c2.w)));
        mxS = fmaxf(mxS, fmaxf(fmaxf(c2.x, c2.y), fmaxf(c2.z, c2.w)));
    }

    #pragma unroll
    for (int o = 16; o > 0; o >>= 1) {
        mnT = fminf(mnT, __shfl_xor_sync(0xffffffffu, mnT, o));
        mxT = fmaxf(mxT, __shfl_xor_sync(0xffffffffu, mxT, o));
        mnS = fminf(mnS, __shfl_xor_sync(0xffffffffu, mnS, o));
        mxS = fmaxf(mxS, __shfl_xor_sync(0xffffffffu, mxS, o));
    }
    __shared__ float sm[4][32];
    int w = threadIdx.x >> 5;
    if ((threadIdx.x & 31) == 0) {
        sm[0][w] = mnT; sm[1][w] = mxT; sm[2][w] = mnS; sm[3][w] = mxS;
    }
    __syncthreads();
    if (threadIdx.x == 0) {
        float a = sm[0][0], c = sm[1][0], e = sm[2][0], f = sm[3][0];
        #pragma unroll
        for (int k = 1; k < 32; k++) {
            a = fminf(a, sm[0][k]); c = fmaxf(c, sm[1][k]);
            e = fminf(e, sm[2][k]); f = fmaxf(f, sm[3][k]);
        }
        int slot = b * MM_CTAS + blockIdx.x;
        g_pmnT[slot] = a; g_pmxT[slot] = c;
        g_pmnS[slot] = e; g_pmxS[slot] = f;
    }
}

// ---------------------------------------------------------------------------
// 2-wide Gaussian window, 2 EX2. Lower clamp REQUIRED (f can round < 0).
__device__ __forceinline__ void gauss2(float f, int& i0, float& w0, float& w1) {
    float i0f = fminf(fmaxf(floorf(f), 0.0f), (float)(NB - 2));
    i0 = (int)i0f;
    float m  = f - i0f;
    float e0 = -EXP2_C * (m * m);
    float e1 = fmaf(EXP2_2C, m, e0 - EXP2_C);   // e0 + C(2m - 1), exp2 domain
    w0 = exp2f(e0);
    w1 = exp2f(e1);
}

// Process one float4-pair (4 points) into the lane-interleaved histogram.
__device__ __forceinline__ void hist4(float4 tv, float4 sv,
                                      float scT, float offT,
                                      float scS, float offS,
                                      float* hb) {
    float tf[4] = {tv.x, tv.y, tv.z, tv.w};
    float sf[4] = {sv.x, sv.y, sv.z, sv.w};
    #pragma unroll
    for (int q = 0; q < 4; q++) {
        float ft = fmaf(tf[q], scT, offT);
        float fs = fmaf(sf[q], scS, offS);
        int it0, js0;
        float wt0, wt1, ws0, ws1;
        gauss2(ft, it0, wt0, wt1);
        gauss2(fs, js0, ws0, ws1);

        float* base = hb + ((it0 * NB + js0) << 5);
        atomicAdd(base,                    wt0 * ws0);
        atomicAdd(base + NCOPY,            wt0 * ws1);
        atomicAdd(base + NB * NCOPY,       wt1 * ws0);
        atomicAdd(base + (NB + 1) * NCOPY, wt1 * ws1);
    }
}

// ---------------------------------------------------------------------------
// Pass 2: joint histogram (2x2 window, 4 conflict-free lane-ATOMS per point).
// 512 threads/CTA -> 128-reg budget -> 6 load-pairs (12 LDG.128) in flight,
// prefetching 6 more inside the slot loop. 32 lane copies, 1 CTA/SM.
// Fused last-CTA finalize.
__global__ void __launch_bounds__(HTHR, 1) k_hist(const float* __restrict__ tar,
                                                  const float* __restrict__ src,
                                                  float* __restrict__ out) {
    extern __shared__ float sh[];           // [NBINS2][32] lane-interleaved
    const int b = blockIdx.y;
    const int tid = threadIdx.x;
    const int lane = tid & 31;

    float4* z4 = (float4*)sh;
    #pragma unroll
    for (int i = tid; i < NBINS2 * NCOPY / 4; i += HTHR)
        z4[i] = make_float4(0.f, 0.f, 0.f, 0.f);

    __shared__ float lim[4];
    if (tid < 4) {
        const float* arr = (tid == 0) ? g_pmnT : (tid == 1) ? g_pmxT :
                           (tid == 2) ? g_pmnS : g_pmxS;
        bool ismin = (tid & 1) == 0;
        float r = __ldcg(&arr[b * MM_CTAS]);
        #pragma unroll 8
        for (int i = 1; i < MM_CTAS; i++) {
            float v = __ldcg(&arr[b * MM_CTAS + i]);
            r = ismin ? fminf(r, v) : fmaxf(r, v);
        }
        lim[tid] = r;
    }

    // 221184 / 18944 = 11.67 -> iterations 0..10 always valid, iter 11 guarded.
    const float4* t4 = (const float4*)(tar + (size_t)b * P_ELEMS);
    const float4* s4 = (const float4*)(src + (size_t)b * P_ELEMS);
    const int n4 = P_ELEMS / 4;             // 221184
    const int base = blockIdx.x * HTHR + tid;

    // Pre-issue 6 pairs (iters 0..5) before the barrier — 12 LDG.128 in flight.
    float4 tb[6], sb[6];
    #pragma unroll
    for (int k = 0; k < 6; k++) {
        tb[k] = t4[base + k * HSTEP];
        sb[k] = s4[base + k * HSTEP];
    }

    __syncthreads();

    const float scT = 31.0f / (lim[1] - lim[0] + 1e-12f);
    const float scS = 31.0f / (lim[3] - lim[2] + 1e-12f);
    const float offT = -lim[0] * scT;
    const float offS = -lim[2] * scS;

    float* hb = sh + lane;                  // this lane's copy base

    // Slots 0..4: process iter k, prefetch iter k+6 (6..10, always valid).
    #pragma unroll
    for (int k = 0; k < 5; k++) {
        hist4(tb[k], sb[k], scT, offT, scS, offS, hb);
        const int idx = base + (k + 6) * HSTEP;
        tb[k] = t4[idx];
        sb[k] = s4[idx];
    }
    // Slot 5: process iter 5, prefetch iter 11 (guarded).
    hist4(tb[5], sb[5], scT, offT, scS, offS, hb);
    const int i11 = base + 11 * HSTEP;
    const bool has12 = (i11 < n4);
    if (has12) { tb[5] = t4[i11]; sb[5] = s4[i11]; }
    // Slots 6..10 + guarded 11.
    #pragma unroll
    for (int k = 0; k < 5; k++)
        hist4(tb[k], sb[k], scT, offT, scS, offS, hb);
    if (has12)
        hist4(tb[5], sb[5], scT, offT, scS, offS, hb);

    __syncthreads();
    // merge NCOPY copies per bin (rotated reads, conflict-free), 2 bins/thread
    #pragma unroll
    for (int bin = tid; bin < NBINS2; bin += HTHR) {
        const float* c = sh + (bin << 5);
        float s = 0.0f;
        #pragma unroll
        for (int i = 0; i < NCOPY; i++) s += c[(lane + i) & (NCOPY - 1)];
        atomicAdd(&g_hist[b * NBINS2 + bin], s);
    }
    __threadfence();
    __syncthreads();

    // ---- last-CTA finalize (completion ticket, whole-CTA uniform branch) ----
    __shared__ unsigned s_rank;
    if (tid == 0) s_rank = atomicAdd(&g_tick, 1u);
    __syncthreads();

    if (s_rank == H_CTAS * NSAMP - 1) {
        float (*smp)[33] = (float(*)[33])sh;     // reuse smem: [4*32][33]
        __shared__ float part[4];

        if (tid < 128) {
            const int w = tid >> 5, ln = tid & 31;

            float v[32];
            #pragma unroll
            for (int i = 0; i < 32; i++)
                v[i] = __ldcg(&g_hist[w * NBINS2 + i * NB + ln]);  // column 'ln'

            float cs = 0.0f;
            #pragma unroll
            for (int i = 0; i < 32; i++) cs += v[i];
            float norm = cs;
            #pragma unroll
            for (int o = 16; o > 0; o >>= 1)
                norm += __shfl_xor_sync(0xffffffffu, norm, o);
            float inv = __frcp_rn(norm);

            float ej = 0.0f;
            #pragma unroll
            for (int i = 0; i < 32; i++) {
                float p = v[i] * inv;
                smp[w * 32 + i][ln] = p;
                ej += p * __logf(p + EPS);
            }
            #pragma unroll
            for (int o = 16; o > 0; o >>= 1)
                ej += __shfl_xor_sync(0xffffffffu, ej, o);

            float q = cs * inv;
            float es = q * __logf(q + EPS);
            #pragma unroll
            for (int o = 16; o > 0; o >>= 1)
                es += __shfl_xor_sync(0xffffffffu, es, o);

            __syncwarp();
            float r = 0.0f;
            #pragma unroll
            for (int j = 0; j < 32; j++) r += smp[w * 32 + ln][j];
            float et = r * __logf(r + EPS);
            #pragma unroll
            for (int o = 16; o > 0; o >>= 1)
                et += __shfl_xor_sync(0xffffffffu, et, o);

            if (ln == 0) part[w] = (et + es) / ej;
        }
        __syncthreads();     // real block barrier before thread 0 reads part[]
        if (tid == 0) {
            out[0] = -(part[0] + part[1] + part[2] + part[3]) * 0.25f;
            g_tick = 0u;            // reset for next graph replay
        }
    }
}

// ---------------------------------------------------------------------------
extern "C" void kernel_launch(void* const* d_in, const int* in_sizes, int n_in,
                              void* d_out, int out_size) {
    const float* tar = (const float*)d_in[0];
    const float* src = (const float*)d_in[1];
    float* out = (float*)d_out;

    static bool attr_set = false;
    if (!attr_set) {
        cudaFuncSetAttribute(k_hist, cudaFuncAttributeMaxDynamicSharedMemorySize,
                             NBINS2 * NCOPY * sizeof(float));
        attr_set = true;
    }

    k_pre<<<dim3(MM_CTAS, NSAMP), 1024>>>(tar, src);
    k_hist<<<dim3(H_CTAS, NSAMP), HTHR, NBINS2 * NCOPY * sizeof(float)>>>(tar, src, out);
}

// round 14
// speedup vs baseline: 1.1262x; 1.1262x over previous
#include <cuda_runtime.h>
#include <cstdint>

// ---------------------------------------------------------------------------
#define P_ELEMS (96*96*96)          // 884736 points per sample
#define NSAMP   4
#define NB      32
#define NBINS2  (NB*NB)
#define MM_CTAS 74                  // minmax CTAs per sample
#define H_CTAS  36                  // hist CTAs per sample (36*24576 = 884736)
#define NCOPY   32                  // lane copies per hist CTA (128 KB)
#define TILE_PTS   4096             // points per staged tile (1 float4/thread)
#define TILE_BYTES (TILE_PTS*4)     // 16 KB
#define NTILES  6                   // 6*4096 = 24576 points per CTA
#define CHUNK   (TILE_PTS*NTILES)

// C = 2048/961 = 2.1311134235 ; exp2 form: C*log2(e)
#define EXP2_C   3.0745468f
#define EXP2_2C  6.1490936f
#define EPS      1e-10f

// ---------------------------------------------------------------------------
__device__ float    g_pmnT[NSAMP*MM_CTAS];
__device__ float    g_pmxT[NSAMP*MM_CTAS];
__device__ float    g_pmnS[NSAMP*MM_CTAS];
__device__ float    g_pmxS[NSAMP*MM_CTAS];
__device__ float    g_hist[NSAMP*NBINS2];
__device__ unsigned g_tick = 0;     // hist completion ticket

// ---------------------------------------------------------------------------
// mbarrier / bulk-async helpers
__device__ __forceinline__ uint32_t smaddr(const void* p) {
    return (uint32_t)__cvta_generic_to_shared(p);
}
__device__ __forceinline__ void mb_init(uint32_t m, uint32_t cnt) {
    asm volatile("mbarrier.init.shared.b64 [%0], %1;" :: "r"(m), "r"(cnt) : "memory");
}
__device__ __forceinline__ void mb_expect(uint32_t m, uint32_t tx) {
    asm volatile("mbarrier.arrive.expect_tx.shared.b64 _, [%0], %1;"
                 :: "r"(m), "r"(tx) : "memory");
}
__device__ __forceinline__ void bulk_g2s(uint32_t dst, const void* src,
                                         uint32_t bytes, uint32_t m) {
    asm volatile(
        "cp.async.bulk.shared::cta.global.mbarrier::complete_tx::bytes "
        "[%0], [%1], %2, [%3];"
        :: "r"(dst), "l"(src), "r"(bytes), "r"(m) : "memory");
}
__device__ __forceinline__ void mb_wait(uint32_t m, uint32_t parity) {
    uint32_t done;
    do {
        asm volatile(
            "{\n\t.reg .pred p;\n\t"
            "mbarrier.try_wait.parity.acquire.cta.shared::cta.b64 p, [%1], %2;\n\t"
            "selp.b32 %0, 1, 0, p;\n\t}"
            : "=r"(done) : "r"(m), "r"(parity) : "memory");
    } while (!done);
}

// ---------------------------------------------------------------------------
// Pass 1: per-CTA min/max partials (unchanged from R12).
__global__ void __launch_bounds__(1024) k_pre(const float* __restrict__ tar,
                                              const float* __restrict__ src) {
    int b = blockIdx.y;
    if (b == 0) {
        int idx = blockIdx.x * 1024 + threadIdx.x;
        if (idx < NSAMP * NBINS2) g_hist[idx] = 0.0f;
    }

    const float4* t4 = (const float4*)(tar + (size_t)b * P_ELEMS);
    const float4* s4 = (const float4*)(src + (size_t)b * P_ELEMS);
    const int n4 = P_ELEMS / 4;
    const int stride = MM_CTAS * 1024;

    const int i = blockIdx.x * 1024 + threadIdx.x;
    float4 a0 = t4[i],          c0 = s4[i];
    float4 a1 = t4[i + stride], c1 = s4[i + stride];

    float mnT = fminf(fminf(fminf(a0.x, a0.y), fminf(a0.z, a0.w)),
                      fminf(fminf(a1.x, a1.y), fminf(a1.z, a1.w)));
    float mxT = fmaxf(fmaxf(fmaxf(a0.x, a0.y), fmaxf(a0.z, a0.w)),
                      fmaxf(fmaxf(a1.x, a1.y), fmaxf(a1.z, a1.w)));
    float mnS = fminf(fminf(fminf(c0.x, c0.y), fminf(c0.z, c0.w)),
                      fminf(fminf(c1.x, c1.y), fminf(c1.z, c1.w)));
    float mxS = fmaxf(fmaxf(fmaxf(c0.x, c0.y), fmaxf(c0.z, c0.w)),
                      fmaxf(fmaxf(c1.x, c1.y), fmaxf(c1.z, c1.w)));

    const int i2 = i + 2 * stride;
    if (i2 < n4) {
        float4 a2 = t4[i2], c2 = s4[i2];
        mnT = fminf(mnT, fminf(fminf(a2.x, a2.y), fminf(a2.z, a2.w)));
        mxT = fmaxf(mxT, fmaxf(fmaxf(a2.x, a2.y), fmaxf(a2.z, a2.w)));
        mnS = fminf(mnS, fminf(fminf(c2.x, c2.y), fminf(c2.z, c2.w)));
        mxS = fmaxf(mxS, fmaxf(fmaxf(c2.x, c2.y), fmaxf(c2.z, c2.w)));
    }

    #pragma unroll
    for (int o = 16; o > 0; o >>= 1) {
        mnT = fminf(mnT, __shfl_xor_sync(0xffffffffu, mnT, o));
        mxT = fmaxf(mxT, __shfl_xor_sync(0xffffffffu, mxT, o));
        mnS = fminf(mnS, __shfl_xor_sync(0xffffffffu, mnS, o));
        mxS = fmaxf(mxS, __shfl_xor_sync(0xffffffffu, mxS, o));
    }
    __shared__ float sm[4][32];
    int w = threadIdx.x >> 5;
    if ((threadIdx.x & 31) == 0) {
        sm[0][w] = mnT; sm[1][w] = mxT; sm[2][w] = mnS; sm[3][w] = mxS;
    }
    __syncthreads();
    if (threadIdx.x == 0) {
        float a = sm[0][0], c = sm[1][0], e = sm[2][0], f = sm[3][0];
        #pragma unroll
        for (int k = 1; k < 32; k++) {
            a = fminf(a, sm[0][k]); c = fmaxf(c, sm[1][k]);
            e = fminf(e, sm[2][k]); f = fmaxf(f, sm[3][k]);
        }
        int slot = b * MM_CTAS + blockIdx.x;
        g_pmnT[slot] = a; g_pmxT[slot] = c;
        g_pmnS[slot] = e; g_pmxS[slot] = f;
    }
}

// ---------------------------------------------------------------------------
// 2-wide Gaussian window, 2 EX2. Lower clamp REQUIRED (f can round < 0).
__device__ __forceinline__ void gauss2(float f, int& i0, float& w0, float& w1) {
    float i0f = fminf(fmaxf(floorf(f), 0.0f), (float)(NB - 2));
    i0 = (int)i0f;
    float m  = f - i0f;
    float e0 = -EXP2_C * (m * m);
    float e1 = fmaf(EXP2_2C, m, e0 - EXP2_C);
    w0 = exp2f(e0);
    w1 = exp2f(e1);
}

__device__ __forceinline__ void hist4(float4 tv, float4 sv,
                                      float scT, float offT,
                                      float scS, float offS,
                                      float* hb) {
    float tf[4] = {tv.x, tv.y, tv.z, tv.w};
    float sf[4] = {sv.x, sv.y, sv.z, sv.w};
    #pragma unroll
    for (int q = 0; q < 4; q++) {
        float ft = fmaf(tf[q], scT, offT);
        float fs = fmaf(sf[q], scS, offS);
        int it0, js0;
        float wt0, wt1, ws0, ws1;
        gauss2(ft, it0, wt0, wt1);
        gauss2(fs, js0, ws0, ws1);

        float* base = hb + ((it0 * NB + js0) << 5);
        atomicAdd(base,                    wt0 * ws0);
        atomicAdd(base + NCOPY,            wt0 * ws1);
        atomicAdd(base + NB * NCOPY,       wt1 * ws0);
        atomicAdd(base + (NB + 1) * NCOPY, wt1 * ws1);
    }
}

// ---------------------------------------------------------------------------
// Pass 2: joint histogram with bulk-async double-buffered input staging.
// smem: [hist 128K][tbuf 2x16K][sbuf 2x16K] = 192 KB. 1024 thr, 1 CTA/SM.
__global__ void __launch_bounds__(1024, 1) k_hist(const float* __restrict__ tar,
                                                  const float* __restrict__ src,
                                                  float* __restrict__ out) {
    extern __shared__ float sh[];
    float* tbuf = sh + NBINS2 * NCOPY;          // 2 * TILE_PTS floats
    float* sbuf = tbuf + 2 * TILE_PTS;          // 2 * TILE_PTS floats
    __shared__ uint64_t mbar[2];
    __shared__ float lim[4];

    const int b = blockIdx.y;
    const int tid = threadIdx.x;
    const int lane = tid & 31;

    const float* tsrc = tar + (size_t)b * P_ELEMS + (size_t)blockIdx.x * CHUNK;
    const float* ssrc = src + (size_t)b * P_ELEMS + (size_t)blockIdx.x * CHUNK;

    const uint32_t mb[2] = { smaddr(&mbar[0]), smaddr(&mbar[1]) };
    const uint32_t tb[2] = { smaddr(tbuf), smaddr(tbuf + TILE_PTS) };
    const uint32_t sb[2] = { smaddr(sbuf), smaddr(sbuf + TILE_PTS) };

    // tid 0: init barriers and kick off tiles 0 and 1 immediately.
    if (tid == 0) {
        mb_init(mb[0], 1);
        mb_init(mb[1], 1);
        mb_expect(mb[0], 2 * TILE_BYTES);
        bulk_g2s(tb[0], tsrc,            TILE_BYTES, mb[0]);
        bulk_g2s(sb[0], ssrc,            TILE_BYTES, mb[0]);
        mb_expect(mb[1], 2 * TILE_BYTES);
        bulk_g2s(tb[1], tsrc + TILE_PTS, TILE_BYTES, mb[1]);
        bulk_g2s(sb[1], ssrc + TILE_PTS, TILE_BYTES, mb[1]);
    }

    // zero the 128 KB histogram while transfers fly
    float4* z4 = (float4*)sh;
    #pragma unroll
    for (int i = tid; i < NBINS2 * NCOPY / 4; i += 1024)
        z4[i] = make_float4(0.f, 0.f, 0.f, 0.f);

    if (tid < 4) {
        const float* arr = (tid == 0) ? g_pmnT : (tid == 1) ? g_pmxT :
                           (tid == 2) ? g_pmnS : g_pmxS;
        bool ismin = (tid & 1) == 0;
        float r = __ldcg(&arr[b * MM_CTAS]);
        #pragma unroll 8
        for (int i = 1; i < MM_CTAS; i++) {
            float v = __ldcg(&arr[b * MM_CTAS + i]);
            r = ismin ? fminf(r, v) : fmaxf(r, v);
        }
        lim[tid] = r;
    }
    __syncthreads();   // hist zeroed, lim ready, mbarriers visible to all

    const float scT = 31.0f / (lim[1] - lim[0] + 1e-12f);
    const float scS = 31.0f / (lim[3] - lim[2] + 1e-12f);
    const float offT = -lim[0] * scT;
    const float offS = -lim[2] * scS;

    float* hb = sh + lane;                  // this lane's copy base

    #pragma unroll
    for (int k = 0; k < NTILES; k++) {
        const int buf = k & 1;
        mb_wait(mb[buf], (k >> 1) & 1);

        float4 tv = ((const float4*)(tbuf + buf * TILE_PTS))[tid];
        float4 sv = ((const float4*)(sbuf + buf * TILE_PTS))[tid];
        hist4(tv, sv, scT, offT, scS, offS, hb);

        __syncthreads();    // everyone done reading this buffer
        if (k + 2 < NTILES && tid == 0) {
            mb_expect(mb[buf], 2 * TILE_BYTES);
            bulk_g2s(tb[buf], tsrc + (k + 2) * TILE_PTS, TILE_BYTES, mb[buf]);
            bulk_g2s(sb[buf], ssrc + (k + 2) * TILE_PTS, TILE_BYTES, mb[buf]);
        }
    }

    __syncthreads();
    // merge NCOPY copies per bin (rotated reads, conflict-free), 1 bin/thread
    {
        const float* c = sh + (tid << 5);
        float s = 0.0f;
        #pragma unroll
        for (int i = 0; i < NCOPY; i++) s += c[(lane + i) & (NCOPY - 1)];
        atomicAdd(&g_hist[b * NBINS2 + tid], s);
    }
    __threadfence();
    __syncthreads();

    // ---- last-CTA finalize ----
    __shared__ unsigned s_rank;
    if (tid == 0) s_rank = atomicAdd(&g_tick, 1u);
    __syncthreads();

    if (s_rank == H_CTAS * NSAMP - 1) {
        float (*smp)[33] = (float(*)[33])sh;     // reuse smem: [4*32][33]
        __shared__ float part[4];

        if (tid < 128) {
            const int w = tid >> 5, ln = tid & 31;

            float v[32];
            #pragma unroll
            for (int i = 0; i < 32; i++)
                v[i] = __ldcg(&g_hist[w * NBINS2 + i * NB + ln]);

            float cs = 0.0f;
            #pragma unroll
            for (int i = 0; i < 32; i++) cs += v[i];
            float norm = cs;
            #pragma unroll
            for (int o = 16; o > 0; o >>= 1)
                norm += __shfl_xor_sync(0xffffffffu, norm, o);
            float inv = __frcp_rn(norm);

            float ej = 0.0f;
            #pragma unroll
            for (int i = 0; i < 32; i++) {
                float p = v[i] * inv;
                smp[w * 32 + i][ln] = p;
                ej += p * __logf(p + EPS);
            }
            #pragma unroll
            for (int o = 16; o > 0; o >>= 1)
                ej += __shfl_xor_sync(0xffffffffu, ej, o);

            float q = cs * inv;
            float es = q * __logf(q + EPS);
            #pragma unroll
            for (int o = 16; o > 0; o >>= 1)
                es += __shfl_xor_sync(0xffffffffu, es, o);

            __syncwarp();
            float r = 0.0f;
            #pragma unroll
            for (int j = 0; j < 32; j++) r += smp[w * 32 + ln][j];
            float et = r * __logf(r + EPS);
            #pragma unroll
            for (int o = 16; o > 0; o >>= 1)
                et += __shfl_xor_sync(0xffffffffu, et, o);

            if (ln == 0) part[w] = (et + es) / ej;
        }
        __syncthreads();     // block barrier before thread 0 reads part[]
        if (tid == 0) {
            out[0] = -(part[0] + part[1] + part[2] + part[3]) * 0.25f;
            g_tick = 0u;            // reset for next graph replay
        }
    }
}

// ---------------------------------------------------------------------------
extern "C" void kernel_launch(void* const* d_in, const int* in_sizes, int n_in,
                              void* d_out, int out_size) {
    const float* tar = (const float*)d_in[0];
    const float* src = (const float*)d_in[1];
    float* out = (float*)d_out;

    const int smem = (NBINS2 * NCOPY + 4 * TILE_PTS) * sizeof(float); // 192 KB

    static bool attr_set = false;
    if (!attr_set) {
        cudaFuncSetAttribute(k_hist, cudaFuncAttributeMaxDynamicSharedMemorySize,
                             smem);
        attr_set = true;
    }

    k_pre<<<dim3(MM_CTAS, NSAMP), 1024>>>(tar, src);
    k_hist<<<dim3(H_CTAS, NSAMP), 1024, smem>>>(tar, src, out);
}

// round 15
// speedup vs baseline: 1.2296x; 1.0918x over previous
#include <cuda_runtime.h>

// ---------------------------------------------------------------------------
#define P_ELEMS (96*96*96)          // 884736 points per sample
#define NSAMP   4
#define NB      32
#define NBINS2  (NB*NB)
#define MM_CTAS 74                  // minmax CTAs per sample
#define H_CTAS  37                  // hist CTAs per sample (37*4=148, 1/SM)
#define NCOPY   32                  // lane copies per hist CTA (128 KB)
#define HSTRIDE (H_CTAS*1024)       // 37888 float4s

// C = 2048/961 = 2.1311134235 ; exp2 form: C*log2(e)
#define EXP2_C   3.0745468f
#define EXP2_2C  6.1490936f
#define EPS      1e-10f

// ---------------------------------------------------------------------------
// Device scratch (no allocations allowed)
__device__ float    g_pmnT[NSAMP*MM_CTAS];
__device__ float    g_pmxT[NSAMP*MM_CTAS];
__device__ float    g_pmnS[NSAMP*MM_CTAS];
__device__ float    g_pmxS[NSAMP*MM_CTAS];
__device__ float    g_hist[NSAMP*NBINS2];
__device__ unsigned g_tick = 0;     // hist completion ticket

// Raw MUFU EX2 — exp2f() WITHOUT fast-math expands to a multi-inst accurate
// routine; this guarantees a single-instruction approx EX2.
__device__ __forceinline__ float ex2(float x) {
    float y;
    asm("ex2.approx.ftz.f32 %0, %1;" : "=f"(y) : "f"(x));
    return y;
}

// ---------------------------------------------------------------------------
// Pass 1: per-CTA min/max partials. Batched independent LDG.128 for MLP.
__global__ void __launch_bounds__(1024) k_pre(const float* __restrict__ tar,
                                              const float* __restrict__ src) {
    int b = blockIdx.y;
    if (b == 0) {
        int idx = blockIdx.x * 1024 + threadIdx.x;
        if (idx < NSAMP * NBINS2) g_hist[idx] = 0.0f;
    }

    const float4* t4 = (const float4*)(tar + (size_t)b * P_ELEMS);
    const float4* s4 = (const float4*)(src + (size_t)b * P_ELEMS);
    const int n4 = P_ELEMS / 4;                 // 221184
    const int stride = MM_CTAS * 1024;          // 75776

    const int i = blockIdx.x * 1024 + threadIdx.x;
    float4 a0 = t4[i],          c0 = s4[i];
    float4 a1 = t4[i + stride], c1 = s4[i + stride];

    float mnT = fminf(fminf(fminf(a0.x, a0.y), fminf(a0.z, a0.w)),
                      fminf(fminf(a1.x, a1.y), fminf(a1.z, a1.w)));
    float mxT = fmaxf(fmaxf(fmaxf(a0.x, a0.y), fmaxf(a0.z, a0.w)),
                      fmaxf(fmaxf(a1.x, a1.y), fmaxf(a1.z, a1.w)));
    float mnS = fminf(fminf(fminf(c0.x, c0.y), fminf(c0.z, c0.w)),
                      fminf(fminf(c1.x, c1.y), fminf(c1.z, c1.w)));
    float mxS = fmaxf(fmaxf(fmaxf(c0.x, c0.y), fmaxf(c0.z, c0.w)),
                      fmaxf(fmaxf(c1.x, c1.y), fmaxf(c1.z, c1.w)));

    const int i2 = i + 2 * stride;
    if (i2 < n4) {
        float4 a2 = t4[i2], c2 = s4[i2];
        mnT = fminf(mnT, fminf(fminf(a2.x, a2.y), fminf(a2.z, a2.w)));
        mxT = fmaxf(mxT, fmaxf(fmaxf(a2.x, a2.y), fmaxf(a2.z, a2.w)));
        mnS = fminf(mnS, fminf(fminf(c2.x, c2.y), fminf(c2.z, c2.w)));
        mxS = fmaxf(mxS, fmaxf(fmaxf(c2.x, c2.y), fmaxf(c2.z, c2.w)));
    }

    #pragma unroll
    for (int o = 16; o > 0; o >>= 1) {
        mnT = fminf(mnT, __shfl_xor_sync(0xffffffffu, mnT, o));
        mxT = fmaxf(mxT, __shfl_xor_sync(0xffffffffu, mxT, o));
        mnS = fminf(mnS, __shfl_xor_sync(0xffffffffu, mnS, o));
        mxS = fmaxf(mxS, __shfl_xor_sync(0xffffffffu, mxS, o));
    }
    __shared__ float sm[4][32];
    int w = threadIdx.x >> 5;
    if ((threadIdx.x & 31) == 0) {
        sm[0][w] = mnT; sm[1][w] = mxT; sm[2][w] = mnS; sm[3][w] = mxS;
    }
    __syncthreads();
    if (threadIdx.x == 0) {
        float a = sm[0][0], c = sm[1][0], e = sm[2][0], f = sm[3][0];
        #pragma unroll
        for (int k = 1; k < 32; k++) {
            a = fminf(a, sm[0][k]); c = fmaxf(c, sm[1][k]);
            e = fminf(e, sm[2][k]); f = fmaxf(f, sm[3][k]);
        }
        int slot = b * MM_CTAS + blockIdx.x;
        g_pmnT[slot] = a; g_pmxT[slot] = c;
        g_pmnS[slot] = e; g_pmxS[slot] = f;
    }
}

// ---------------------------------------------------------------------------
// 2-wide Gaussian window, 2 raw EX2. Lower clamp REQUIRED (f can round < 0).
__device__ __forceinline__ void gauss2(float f, int& i0, float& w0, float& w1) {
    float i0f = fminf(fmaxf(floorf(f), 0.0f), (float)(NB - 2));
    i0 = (int)i0f;
    float m  = f - i0f;
    float e0 = -EXP2_C * (m * m);
    float e1 = fmaf(EXP2_2C, m, e0 - EXP2_C);   // e0 + C(2m - 1), exp2 domain
    w0 = ex2(e0);
    w1 = ex2(e1);
}

// Process one float4-pair (4 points) into the lane-interleaved histogram.
__device__ __forceinline__ void hist4(float4 tv, float4 sv,
                                      float scT, float offT,
                                      float scS, float offS,
                                      float* hb) {
    float tf[4] = {tv.x, tv.y, tv.z, tv.w};
    float sf[4] = {sv.x, sv.y, sv.z, sv.w};
    #pragma unroll
    for (int q = 0; q < 4; q++) {
        float ft = fmaf(tf[q], scT, offT);
        float fs = fmaf(sf[q], scS, offS);
        int it0, js0;
        float wt0, wt1, ws0, ws1;
        gauss2(ft, it0, wt0, wt1);
        gauss2(fs, js0, ws0, ws1);

        float* base = hb + ((it0 * NB + js0) << 5);
        atomicAdd(base,                    wt0 * ws0);
        atomicAdd(base + NCOPY,            wt0 * ws1);
        atomicAdd(base + NB * NCOPY,       wt1 * ws0);
        atomicAdd(base + (NB + 1) * NCOPY, wt1 * ws1);
    }
}

// ---------------------------------------------------------------------------
// Pass 2: joint histogram (2x2 window, 4 conflict-free lane-ATOMS per point),
// statically software-pipelined loads (3 rotating buffers, 6 fixed slots),
// + fused last-CTA finalize. 32 lane copies (128 KB), 1 CTA/SM.
__global__ void __launch_bounds__(1024, 1) k_hist(const float* __restrict__ tar,
                                                  const float* __restrict__ src,
                                                  float* __restrict__ out) {
    extern __shared__ float sh[];           // [NBINS2][32] lane-interleaved
    const int b = blockIdx.y;
    const int tid = threadIdx.x;
    const int lane = tid & 31;

    float4* z4 = (float4*)sh;
    #pragma unroll
    for (int i = tid; i < NBINS2 * NCOPY / 4; i += 1024)
        z4[i] = make_float4(0.f, 0.f, 0.f, 0.f);

    __shared__ float lim[4];
    if (tid < 4) {
        const float* arr = (tid == 0) ? g_pmnT : (tid == 1) ? g_pmxT :
                           (tid == 2) ? g_pmnS : g_pmxS;
        bool ismin = (tid & 1) == 0;
        float r = __ldcg(&arr[b * MM_CTAS]);
        #pragma unroll 8
        for (int i = 1; i < MM_CTAS; i++) {
            float v = __ldcg(&arr[b * MM_CTAS + i]);
            r = ismin ? fminf(r, v) : fmaxf(r, v);
        }
        lim[tid] = r;
    }

    // Issue the first 3 load pairs BEFORE the barrier (always in range).
    const float4* t4 = (const float4*)(tar + (size_t)b * P_ELEMS);
    const float4* s4 = (const float4*)(src + (size_t)b * P_ELEMS);
    const int n4 = P_ELEMS / 4;             // 221184
    const int base = blockIdx.x * 1024 + tid;

    float4 ta0 = t4[base],               sa0 = s4[base];
    float4 ta1 = t4[base + HSTRIDE],     sa1 = s4[base + HSTRIDE];
    float4 ta2 = t4[base + 2 * HSTRIDE], sa2 = s4[base + 2 * HSTRIDE];

    __syncthreads();

    const float scT = 31.0f / (lim[1] - lim[0] + 1e-12f);
    const float scS = 31.0f / (lim[3] - lim[2] + 1e-12f);
    const float offT = -lim[0] * scT;
    const float offS = -lim[2] * scS;

    float* hb = sh + lane;                  // this lane's copy base

    const int f5 = base + 5 * HSTRIDE;
    const bool has6 = (f5 < n4);

    // slot 0: process iter0, prefetch iter3
    hist4(ta0, sa0, scT, offT, scS, offS, hb);
    ta0 = t4[base + 3 * HSTRIDE]; sa0 = s4[base + 3 * HSTRIDE];
    // slot 1: process iter1, prefetch iter4
    hist4(ta1, sa1, scT, offT, scS, offS, hb);
    ta1 = t4[base + 4 * HSTRIDE]; sa1 = s4[base + 4 * HSTRIDE];
    // slot 2: process iter2, prefetch iter5 (guarded)
    hist4(ta2, sa2, scT, offT, scS, offS, hb);
    if (has6) { ta2 = t4[f5]; sa2 = s4[f5]; }
    // slots 3..5
    hist4(ta0, sa0, scT, offT, scS, offS, hb);
    hist4(ta1, sa1, scT, offT, scS, offS, hb);
    if (has6) hist4(ta2, sa2, scT, offT, scS, offS, hb);

    __syncthreads();
    // merge NCOPY copies per bin (rotated reads, conflict-free), 1 bin/thread
    {
        const float* c = sh + (tid << 5);
        float s = 0.0f;
        #pragma unroll
        for (int i = 0; i < NCOPY; i++) s += c[(lane + i) & (NCOPY - 1)];
        atomicAdd(&g_hist[b * NBINS2 + tid], s);
    }
    __threadfence();
    __syncthreads();

    // ---- last-CTA finalize (completion ticket, whole-CTA uniform branch) ----
    __shared__ unsigned s_rank;
    if (tid == 0) s_rank = atomicAdd(&g_tick, 1u);
    __syncthreads();

    if (s_rank == H_CTAS * NSAMP - 1) {
        float (*smp)[33] = (float(*)[33])sh;     // reuse smem: [4*32][33]
        __shared__ float part[4];

        if (tid < 128) {
            const int w = tid >> 5, ln = tid & 31;

            float v[32];
            #pragma unroll
            for (int i = 0; i < 32; i++)
                v[i] = __ldcg(&g_hist[w * NBINS2 + i * NB + ln]);  // column 'ln'

            float cs = 0.0f;
            #pragma unroll
            for (int i = 0; i < 32; i++) cs += v[i];
            float norm = cs;
            #pragma unroll
            for (int o = 16; o > 0; o >>= 1)
                norm += __shfl_xor_sync(0xffffffffu, norm, o);
            float inv = __frcp_rn(norm);

            float ej = 0.0f;
            #pragma unroll
            for (int i = 0; i < 32; i++) {
                float p = v[i] * inv;
                smp[w * 32 + i][ln] = p;
                ej += p * __logf(p + EPS);
            }
            #pragma unroll
            for (int o = 16; o > 0; o >>= 1)
                ej += __shfl_xor_sync(0xffffffffu, ej, o);

            float q = cs * inv;
            float es = q * __logf(q + EPS);
            #pragma unroll
            for (int o = 16; o > 0; o >>= 1)
                es += __shfl_xor_sync(0xffffffffu, es, o);

            __syncwarp();
            float r = 0.0f;
            #pragma unroll
            for (int j = 0; j < 32; j++) r += smp[w * 32 + ln][j];
            float et = r * __logf(r + EPS);
            #pragma unroll
            for (int o = 16; o > 0; o >>= 1)
                et += __shfl_xor_sync(0xffffffffu, et, o);

            if (ln == 0) part[w] = (et + es) / ej;
        }
        __syncthreads();     // real block barrier before thread 0 reads part[]
        if (tid == 0) {
            out[0] = -(part[0] + part[1] + part[2] + part[3]) * 0.25f;
            g_tick = 0u;            // reset for next graph replay
        }
    }
}

// ---------------------------------------------------------------------------
extern "C" void kernel_launch(void* const* d_in, const int* in_sizes, int n_in,
                              void* d_out, int out_size) {
    const float* tar = (const float*)d_in[0];
    const float* src = (const float*)d_in[1];
    float* out = (float*)d_out;

    static bool attr_set = false;
    if (!attr_set) {
        cudaFuncSetAttribute(k_hist, cudaFuncAttributeMaxDynamicSharedMemorySize,
                             NBINS2 * NCOPY * sizeof(float));
        attr_set = true;
    }

    k_pre<<<dim3(MM_CTAS, NSAMP), 1024>>>(tar, src);
    k_hist<<<dim3(H_CTAS, NSAMP), 1024, NBINS2 * NCOPY * sizeof(float)>>>(tar, src, out);
}